// round 4
// baseline (speedup 1.0000x reference)
#include <cuda_runtime.h>
#include <cmath>

// ive(v=49.5, z) computed in the SAME factorized form as the reference:
//   out = pref * S,   pref = exp(v*ln(z/2) - lgamma(v+1) - z),   S = exp(lnS(z^2))
// so underflow/denormal double-rounding matches the reference's exp(log_pref)*S.
//
// lnS(s)/ln2 is approximated on s in [0.25, 9900.25] by a degree-16 CHEBYSHEV fit
// (nearest singularity at s ~ -3203 -> Bernstein rho ~ 2.94 -> fit error < 1e-6),
// converted to a monomial Horner in t=(s-s0)/h. Coefficients built on the HOST in
// double at static init and passed by value (constant bank).
//
// pref is computed as ex2(lp2 + 64) * 2^-64 with non-FTZ muls so denormal outputs
// are correctly rounded exactly where the reference's exp() denormalizes.
//
// Hot math: packed fma.rn.f32x2 Horner (2 elems/instr), 3 MUFU/elem (lg2 + 2 ex2).

#define NP  16
#define TPB 256
#define EPT 4

struct QTab { float q[NP + 1]; float c64; };

static QTab make_tab_host() {
    const double VD = 49.5, S0 = 4950.25, HH = 4950.0;
    const double LN2 = 0.69314718055994530942;
    const int M = 64;                       // Chebyshev interpolation nodes
    double f[M];
    for (int j = 0; j < M; j++) {
        double x = std::cos(M_PI * (j + 0.5) / M);
        double s = S0 + HH * x;
        double T = 1.0, sum = 1.0;          // S(s) = sum_k (s/4)^k / (k! (v+1)_k)
        for (int k = 1; k < 700; k++) {
            T *= s / (4.0 * (double)k * (VD + (double)k));
            sum += T;
            if (k > 40 && T < sum * 1e-19) break;
        }
        f[j] = std::log(sum) / LN2;         // lnS / ln2
    }
    double c[NP + 1];
    for (int k = 0; k <= NP; k++) {
        double acc = 0.0;
        for (int j = 0; j < M; j++) acc += f[j] * std::cos(M_PI * k * (j + 0.5) / M);
        c[k] = 2.0 * acc / M;
    }
    c[0] *= 0.5;
    // Chebyshev -> monomial via T_{k+1} = 2 x T_k - T_{k-1}
    double a[NP + 1] = {0}, Tp[NP + 1] = {0}, Tc[NP + 1] = {0}, Tn[NP + 1];
    Tp[0] = 1.0; a[0] += c[0];
    Tc[1] = 1.0; a[1] += c[1];
    for (int k = 2; k <= NP; k++) {
        for (int m = 0; m <= NP; m++) {
            double v = -Tp[m];
            if (m > 0) v += 2.0 * Tc[m - 1];
            Tn[m] = v;
        }
        for (int m = 0; m <= k; m++) a[m] += c[k] * Tn[m];
        for (int m = 0; m <= NP; m++) { Tp[m] = Tc[m]; Tc[m] = Tn[m]; }
    }
    QTab t;
    for (int m = 0; m <= NP; m++) t.q[m] = (float)a[m];
    // lp2 = 49.5*lg2(z) - 49.5 - lgamma(50.5)/ln2 - z/ln2 ; fold +64 bias here
    t.c64 = (float)(-(std::lgamma(50.5) / LN2) - 49.5 + 64.0);
    return t;
}
static const QTab H_Q = make_tab_host();   // host static init only

typedef unsigned long long ull;
__device__ __forceinline__ ull pack2(float a, float b) {
    ull r; asm("mov.b64 %0, {%1, %2};" : "=l"(r) : "f"(a), "f"(b)); return r;
}
__device__ __forceinline__ void unpack2(ull v, float& a, float& b) {
    asm("mov.b64 {%0, %1}, %2;" : "=f"(a), "=f"(b) : "l"(v));
}
__device__ __forceinline__ ull fma2(ull a, ull b, ull c) {
    ull d; asm("fma.rn.f32x2 %0, %1, %2, %3;" : "=l"(d) : "l"(a), "l"(b), "l"(c));
    return d;
}
__device__ __forceinline__ ull mul2(ull a, ull b) {
    ull d; asm("mul.rn.f32x2 %0, %1, %2;" : "=l"(d) : "l"(a), "l"(b)); return d;
}
__device__ __forceinline__ float lg2f(float x) {
    float r; asm("lg2.approx.f32 %0, %1;" : "=f"(r) : "f"(x)); return r;
}
__device__ __forceinline__ float ex2f(float x) {
    float r; asm("ex2.approx.f32 %0, %1;" : "=f"(r) : "f"(x)); return r;
}
__device__ __forceinline__ float mulrn(float a, float b) {   // non-FTZ: keeps denormals
    float r; asm("mul.rn.f32 %0, %1, %2;" : "=f"(r) : "f"(a), "f"(b)); return r;
}

__device__ __forceinline__ float finish(float z, float e, float ps) {
    // pref = exp(log_pref) with correct denormal rounding; then * S (two roundings,
    // matching the reference's exp(log_pref) * S structure).
    float lp   = fmaf(49.5f, lg2f(z), e);            // lp2 + 64
    float pref = mulrn(ex2f(lp), 5.421010862427522e-20f);  // * 2^-64
    return mulrn(pref, ex2f(ps));
}

__global__ void __launch_bounds__(TPB)
ive_kernel(const float* __restrict__ zin, float* __restrict__ out, int n, QTab tab) {
    __shared__ float2 qs[NP + 1];
    if (threadIdx.x <= NP) {
        float v = tab.q[threadIdx.x];
        qs[threadIdx.x] = make_float2(v, v);
    }
    __syncthreads();

    const float HIF = 1.0f / 4950.0f;
    const float HCF = -4950.25f / 4950.0f;
    const ull HI2  = pack2(HIF, HIF);
    const ull HC2  = pack2(HCF, HCF);
    const ull NIL2 = pack2(-1.44269504088896341f, -1.44269504088896341f);
    const ull C642 = pack2(tab.c64, tab.c64);

    int base = (blockIdx.x * TPB + threadIdx.x) * EPT;
    if (base + EPT <= n) {
        float4 a = __ldcs((const float4*)(zin + base));
        ull Z[2] = {pack2(a.x, a.y), pack2(a.z, a.w)};
        ull T[2], R[2];
        {
            float2 qt = qs[NP];
            ull Qt = pack2(qt.x, qt.y);
#pragma unroll
            for (int i = 0; i < 2; i++) {
                T[i] = fma2(mul2(Z[i], Z[i]), HI2, HC2);   // t = (z*z - s0)/h
                R[i] = Qt;
            }
        }
#pragma unroll
        for (int m = NP - 1; m >= 0; m--) {
            float2 qm = qs[m];
            ull Qm = pack2(qm.x, qm.y);                    // LDS.64 broadcast
            R[0] = fma2(R[0], T[0], Qm);
            R[1] = fma2(R[1], T[1], Qm);
        }
        ull E[2] = {fma2(Z[0], NIL2, C642), fma2(Z[1], NIL2, C642)};  // -z/ln2 + c64

        float z0, z1, z2, z3, e0, e1, e2, e3, p0, p1, p2, p3;
        unpack2(Z[0], z0, z1); unpack2(Z[1], z2, z3);
        unpack2(E[0], e0, e1); unpack2(E[1], e2, e3);
        unpack2(R[0], p0, p1); unpack2(R[1], p2, p3);
        float4 r = make_float4(finish(z0, e0, p0), finish(z1, e1, p1),
                               finish(z2, e2, p2), finish(z3, e3, p3));
        __stcs((float4*)(out + base), r);
    } else {
        int end = (n < base + EPT) ? n : base + EPT;
        for (int i = base; i < end; i++) {
            float z = zin[i];
            float t = fmaf(z * z, HIF, HCF);
            float rr = tab.q[NP];
            for (int m = NP - 1; m >= 0; m--) rr = fmaf(rr, t, tab.q[m]);
            float e = fmaf(z, -1.44269504088896341f, tab.c64);
            out[i] = finish(z, e, rr);
        }
    }
}

extern "C" void kernel_launch(void* const* d_in, const int* in_sizes, int n_in,
                              void* d_out, int out_size) {
    const float* z = (const float*)d_in[0];
    float* o = (float*)d_out;
    int n = in_sizes[0];
    if (n <= 0) return;
    int per_block = TPB * EPT;
    int grid = (n + per_block - 1) / per_block;
    ive_kernel<<<grid, TPB>>>(z, o, n, H_Q);
}

// round 5
// speedup vs baseline: 1.0006x; 1.0006x over previous
#include <cuda_runtime.h>
#include <cmath>

// ive(v=49.5, z) = ex2( 49.5*lg2(z) - z/ln2 - lgamma(50.5)/ln2 - 49.5 + lnS(z^2)/ln2 )
// with S(s) = sum_k (s/4)^k / (k! (v+1)_k).
//
// lnS(s)/ln2 on s in [0.25, 9900.25]: degree-16 Chebyshev fit (nearest singularity
// s ~ -3203 -> rho ~ 2.94 -> fit err < 1e-6), monomial Horner in t=(s-s0)/h with
// SMALL coefficients (<= ~60), packed fma.rn.f32x2 (2 elems/instr).
//
// Round-5 change: single ex2 per element (2 MUFU/elem total, was 3) — MUFU pipe
// (rt_SMSP=8) was the hidden saturated pipe at 49.6us. Exponent is biased +64 and
// the result scaled by 2^-64 with a non-FTZ multiply so denormal outputs stay
// correctly rounded where the reference's exp() denormalizes.
//
// Coefficients built on the host in double at static init; passed by value.

#define NP  16
#define TPB 256
#define EPT 4

struct QTab { float q[NP + 1]; float c64; };

static QTab make_tab_host() {
    const double VD = 49.5, S0 = 4950.25, HH = 4950.0;
    const double LN2 = 0.69314718055994530942;
    const int M = 64;
    double f[M];
    for (int j = 0; j < M; j++) {
        double x = std::cos(M_PI * (j + 0.5) / M);
        double s = S0 + HH * x;
        double T = 1.0, sum = 1.0;
        for (int k = 1; k < 700; k++) {
            T *= s / (4.0 * (double)k * (VD + (double)k));
            sum += T;
            if (k > 40 && T < sum * 1e-19) break;
        }
        f[j] = std::log(sum) / LN2;
    }
    double c[NP + 1];
    for (int k = 0; k <= NP; k++) {
        double acc = 0.0;
        for (int j = 0; j < M; j++) acc += f[j] * std::cos(M_PI * k * (j + 0.5) / M);
        c[k] = 2.0 * acc / M;
    }
    c[0] *= 0.5;
    double a[NP + 1] = {0}, Tp[NP + 1] = {0}, Tc[NP + 1] = {0}, Tn[NP + 1];
    Tp[0] = 1.0; a[0] += c[0];
    Tc[1] = 1.0; a[1] += c[1];
    for (int k = 2; k <= NP; k++) {
        for (int m = 0; m <= NP; m++) {
            double v = -Tp[m];
            if (m > 0) v += 2.0 * Tc[m - 1];
            Tn[m] = v;
        }
        for (int m = 0; m <= k; m++) a[m] += c[k] * Tn[m];
        for (int m = 0; m <= NP; m++) { Tp[m] = Tc[m]; Tc[m] = Tn[m]; }
    }
    QTab t;
    for (int m = 0; m <= NP; m++) t.q[m] = (float)a[m];
    // c64 = -lgamma(50.5)/ln2 - 49.5 + 64   (the +64 is the denormal-safe bias)
    t.c64 = (float)(-(std::lgamma(50.5) / LN2) - 49.5 + 64.0);
    return t;
}
static const QTab H_Q = make_tab_host();   // host static init only

typedef unsigned long long ull;
__device__ __forceinline__ ull pack2(float a, float b) {
    ull r; asm("mov.b64 %0, {%1, %2};" : "=l"(r) : "f"(a), "f"(b)); return r;
}
__device__ __forceinline__ void unpack2(ull v, float& a, float& b) {
    asm("mov.b64 {%0, %1}, %2;" : "=f"(a), "=f"(b) : "l"(v));
}
__device__ __forceinline__ ull fma2(ull a, ull b, ull c) {
    ull d; asm("fma.rn.f32x2 %0, %1, %2, %3;" : "=l"(d) : "l"(a), "l"(b), "l"(c));
    return d;
}
__device__ __forceinline__ ull mul2(ull a, ull b) {
    ull d; asm("mul.rn.f32x2 %0, %1, %2;" : "=l"(d) : "l"(a), "l"(b)); return d;
}
__device__ __forceinline__ float lg2f(float x) {
    float r; asm("lg2.approx.f32 %0, %1;" : "=f"(r) : "f"(x)); return r;
}
__device__ __forceinline__ float ex2f(float x) {
    float r; asm("ex2.approx.f32 %0, %1;" : "=f"(r) : "f"(x)); return r;
}
__device__ __forceinline__ float mulrn(float a, float b) {   // non-FTZ multiply
    float r; asm("mul.rn.f32 %0, %1, %2;" : "=f"(r) : "f"(a), "f"(b)); return r;
}

// single-exp finish: out = ex2( 49.5*lg2(z) + (e + p) ) * 2^-64
__device__ __forceinline__ float finish(float z, float e, float p) {
    float g = fmaf(49.5f, lg2f(z), e + p);
    return mulrn(ex2f(g), 5.421010862427522e-20f);   // 2^-64
}

__global__ void __launch_bounds__(TPB)
ive_kernel(const float* __restrict__ zin, float* __restrict__ out, int n, QTab tab) {
    __shared__ float2 qs[NP + 1];
    if (threadIdx.x <= NP) {
        float v = tab.q[threadIdx.x];
        qs[threadIdx.x] = make_float2(v, v);
    }
    __syncthreads();

    const float HIF = 1.0f / 4950.0f;
    const float HCF = -4950.25f / 4950.0f;
    const ull HI2  = pack2(HIF, HIF);
    const ull HC2  = pack2(HCF, HCF);
    const ull NIL2 = pack2(-1.44269504088896341f, -1.44269504088896341f);
    const ull C642 = pack2(tab.c64, tab.c64);

    int base = (blockIdx.x * TPB + threadIdx.x) * EPT;
    if (base + EPT <= n) {
        float4 a = __ldcs((const float4*)(zin + base));
        ull Z0 = pack2(a.x, a.y), Z1 = pack2(a.z, a.w);
        ull T0 = fma2(mul2(Z0, Z0), HI2, HC2);          // t = (z*z - s0)/h
        ull T1 = fma2(mul2(Z1, Z1), HI2, HC2);
        float2 qt = qs[NP];
        ull R0 = pack2(qt.x, qt.y), R1 = R0;
#pragma unroll
        for (int m = NP - 1; m >= 0; m--) {
            float2 qm = qs[m];
            ull Qm = pack2(qm.x, qm.y);                 // LDS.64 broadcast
            R0 = fma2(R0, T0, Qm);
            R1 = fma2(R1, T1, Qm);
        }
        ull E0 = fma2(Z0, NIL2, C642);                  // -z/ln2 + c64
        ull E1 = fma2(Z1, NIL2, C642);

        float e0, e1, e2, e3, p0, p1, p2, p3;
        unpack2(E0, e0, e1); unpack2(E1, e2, e3);
        unpack2(R0, p0, p1); unpack2(R1, p2, p3);
        float4 r = make_float4(finish(a.x, e0, p0), finish(a.y, e1, p1),
                               finish(a.z, e2, p2), finish(a.w, e3, p3));
        __stcs((float4*)(out + base), r);
    } else {
        int end = (n < base + EPT) ? n : base + EPT;
        for (int i = base; i < end; i++) {
            float z = zin[i];
            float t = fmaf(z * z, HIF, HCF);
            float rr = tab.q[NP];
            for (int m = NP - 1; m >= 0; m--) rr = fmaf(rr, t, tab.q[m]);
            float e = fmaf(z, -1.44269504088896341f, tab.c64);
            out[i] = finish(z, e, rr);
        }
    }
}

extern "C" void kernel_launch(void* const* d_in, const int* in_sizes, int n_in,
                              void* d_out, int out_size) {
    const float* z = (const float*)d_in[0];
    float* o = (float*)d_out;
    int n = in_sizes[0];
    if (n <= 0) return;
    int per_block = TPB * EPT;
    int grid = (n + per_block - 1) / per_block;
    ive_kernel<<<grid, TPB>>>(z, o, n, H_Q);
}